// round 9
// baseline (speedup 1.0000x reference)
#include <cuda_runtime.h>
#include <cuda_bf16.h>
#include <math.h>

#define NR   8192     // rows of z
#define HD   256      // feature dim
#define NC   64       // clusters
#define RPB  32       // rows per block
#define TPB  256      // 8 warps: 2 warp_m x 4 warp_n, warp tile m16n16
#define NBLK (NR / RPB)   // 256 blocks, 2 per SM, all resident

// fp32 tiles in smem, row stride 1024B (64 x 16B chunks), XOR-swizzled
#define OFF_Z  0
#define OFF_C  32768
#define SMEM_B 98304

__device__ float g_partT[NC * NBLK];  // transposed partial colsums [col][block]
__device__ unsigned int g_arrive;     // epoch ticket counter (static zero-init)

#define LDSM4(r, addr) \
    asm volatile("ldmatrix.sync.aligned.m8n8.x4.shared.b16 {%0,%1,%2,%3}, [%4];" \
        : "=r"((r)[0]), "=r"((r)[1]), "=r"((r)[2]), "=r"((r)[3]) : "r"(addr))

#define MMA_TF32(d, a, b0, b1) \
    asm volatile("mma.sync.aligned.m16n8k8.row.col.f32.tf32.tf32.f32 " \
        "{%0,%1,%2,%3},{%4,%5,%6,%7},{%8,%9},{%0,%1,%2,%3};" \
        : "+f"((d)[0]), "+f"((d)[1]), "+f"((d)[2]), "+f"((d)[3]) \
        : "r"((a)[0]), "r"((a)[1]), "r"((a)[2]), "r"((a)[3]), "r"(b0), "r"(b1))

__device__ __forceinline__ float fsqrt_ap(float x) {
    float r; asm("sqrt.approx.ftz.f32 %0, %1;" : "=f"(r) : "f"(x)); return r;
}
__device__ __forceinline__ float frcp_ap(float x) {
    float r; asm("rcp.approx.ftz.f32 %0, %1;" : "=f"(r) : "f"(x)); return r;
}
// swizzled byte offset of 16B chunk (row, c) within a tile
__device__ __forceinline__ unsigned swz(int row, int c) {
    return (unsigned)(row * 1024 + (((c ^ (row & 7)) << 4)));
}

__global__ void __launch_bounds__(TPB, 2)
fused_kernel(const float* __restrict__ z, const float* __restrict__ cent,
             float* __restrict__ Q, float* __restrict__ P) {
    extern __shared__ char smem[];
    __shared__ float s_zn[RPB], s_cn[NC];
    __shared__ float s_rs[RPB], s_cs[NC], s_ct[NC], s_pr[RPB];

    const int t = threadIdx.x;

    if (t < NC) { s_cs[t] = 0.f; s_ct[t] = 0.f; }
    if (t < RPB) { s_rs[t] = 0.f; s_pr[t] = 0.f; }

    // ---- Phase 0a: z tile LDG -> norms in regs -> swizzled STS ----
    {
        const int row = t >> 3, c8 = t & 7;        // 32 rows x 8 lanes
        const float4* zg = (const float4*)(z + (size_t)blockIdx.x * RPB * HD + row * HD);
        float4 v[8];
        #pragma unroll
        for (int j = 0; j < 8; j++) v[j] = zg[c8 + 8 * j];
        float acc = 0.f;
        #pragma unroll
        for (int j = 0; j < 8; j++) {
            acc = fmaf(v[j].x, v[j].x, acc);
            acc = fmaf(v[j].y, v[j].y, acc);
            acc = fmaf(v[j].z, v[j].z, acc);
            acc = fmaf(v[j].w, v[j].w, acc);
            *(float4*)(smem + OFF_Z + swz(row, c8 + 8 * j)) = v[j];
        }
        acc += __shfl_xor_sync(0xffffffffu, acc, 1);
        acc += __shfl_xor_sync(0xffffffffu, acc, 2);
        acc += __shfl_xor_sync(0xffffffffu, acc, 4);
        if (c8 == 0) s_zn[row] = acc;
    }

    // ---- Phase 0b: centroid tile LDG -> norms -> swizzled STS ----
    {
        const int row = t >> 2, c4 = t & 3;        // 64 rows x 4 lanes
        const float4* cg = (const float4*)(cent + row * HD);
        float acc = 0.f;
        #pragma unroll
        for (int j = 0; j < 16; j++) {
            float4 v = cg[c4 + 4 * j];
            acc = fmaf(v.x, v.x, acc);
            acc = fmaf(v.y, v.y, acc);
            acc = fmaf(v.z, v.z, acc);
            acc = fmaf(v.w, v.w, acc);
            *(float4*)(smem + OFF_C + swz(row, c4 + 4 * j)) = v;
        }
        acc += __shfl_xor_sync(0xffffffffu, acc, 1);
        acc += __shfl_xor_sync(0xffffffffu, acc, 2);
        if (c4 == 0) s_cn[row] = acc;
    }
    __syncthreads();

    // ---- Phase 2: tf32 GEMM mainloop, warp tile m16n16, k8 per step ----
    const unsigned sb = (unsigned)__cvta_generic_to_shared(smem);
    const int lane = t & 31, wid = t >> 5;
    const int wm = wid >> 2, wn = wid & 3;
    const int tile = lane >> 3, rit = lane & 7;

    const int arow = wm * 16 + 8 * (tile & 1) + rit;
    const int acb = tile >> 1;
    const unsigned abase = sb + OFF_Z + arow * 1024;
    const int axor = arow & 7;

    const int brow = wn * 16 + 8 * (tile >> 1) + rit;
    const int bcb = tile & 1;
    const unsigned bbase = sb + OFF_C + brow * 1024;
    const int bxor = brow & 7;

    float d0[4] = {0.f, 0.f, 0.f, 0.f};   // n-half 0
    float d1[4] = {0.f, 0.f, 0.f, 0.f};   // n-half 1

    #pragma unroll
    for (int ks = 0; ks < 32; ks++) {
        const unsigned aoff = (unsigned)(((2 * ks + acb) ^ axor) << 4);
        const unsigned boff = (unsigned)(((2 * ks + bcb) ^ bxor) << 4);
        unsigned a[4], b[4];
        LDSM4(a, abase + aoff);
        LDSM4(b, bbase + boff);
        MMA_TF32(d0, a, b[0], b[1]);
        MMA_TF32(d1, a, b[2], b[3]);
    }

    // ---- Phase 3: epilogue -> Q ----
    const int gid = lane >> 2, tig = lane & 3;
    const int R0 = wm * 16 + gid, R1 = R0 + 8;
    const float znA = s_zn[R0], znB = s_zn[R1];
    const int c00 = wn * 16 + 2 * tig;
    const int c10 = c00 + 8;
    const float cnA0 = s_cn[c00], cnA1 = s_cn[c00 + 1];
    const float cnB0 = s_cn[c10], cnB1 = s_cn[c10 + 1];

    float q00 = frcp_ap(1.f + fsqrt_ap(fmaxf(fmaf(-2.f, d0[0], znA + cnA0), 0.f)));
    float q01 = frcp_ap(1.f + fsqrt_ap(fmaxf(fmaf(-2.f, d0[1], znA + cnA1), 0.f)));
    float q02 = frcp_ap(1.f + fsqrt_ap(fmaxf(fmaf(-2.f, d0[2], znB + cnA0), 0.f)));
    float q03 = frcp_ap(1.f + fsqrt_ap(fmaxf(fmaf(-2.f, d0[3], znB + cnA1), 0.f)));
    float q10 = frcp_ap(1.f + fsqrt_ap(fmaxf(fmaf(-2.f, d1[0], znA + cnB0), 0.f)));
    float q11 = frcp_ap(1.f + fsqrt_ap(fmaxf(fmaf(-2.f, d1[1], znA + cnB1), 0.f)));
    float q12 = frcp_ap(1.f + fsqrt_ap(fmaxf(fmaf(-2.f, d1[2], znB + cnB0), 0.f)));
    float q13 = frcp_ap(1.f + fsqrt_ap(fmaxf(fmaf(-2.f, d1[3], znB + cnB1), 0.f)));

    float rs0 = (q00 + q01) + (q10 + q11);
    float rs1 = (q02 + q03) + (q12 + q13);
    rs0 += __shfl_xor_sync(0xffffffffu, rs0, 1);
    rs0 += __shfl_xor_sync(0xffffffffu, rs0, 2);
    rs1 += __shfl_xor_sync(0xffffffffu, rs1, 1);
    rs1 += __shfl_xor_sync(0xffffffffu, rs1, 2);
    if (tig == 0) { atomicAdd(&s_rs[R0], rs0); atomicAdd(&s_rs[R1], rs1); }
    __syncthreads();

    const float ir0 = frcp_ap(s_rs[R0]), ir1 = frcp_ap(s_rs[R1]);
    q00 *= ir0; q01 *= ir0; q10 *= ir0; q11 *= ir0;
    q02 *= ir1; q03 *= ir1; q12 *= ir1; q13 *= ir1;

    const int gA = blockIdx.x * RPB + R0;
    const int gB = blockIdx.x * RPB + R1;
    *(float2*)(Q + (size_t)gA * NC + c00) = make_float2(q00, q01);
    *(float2*)(Q + (size_t)gB * NC + c00) = make_float2(q02, q03);
    *(float2*)(Q + (size_t)gA * NC + c10) = make_float2(q10, q11);
    *(float2*)(Q + (size_t)gB * NC + c10) = make_float2(q12, q13);

    float cA0 = q00 + q02, cA1 = q01 + q03;
    float cB0 = q10 + q12, cB1 = q11 + q13;
    #pragma unroll
    for (int m = 4; m <= 16; m <<= 1) {
        cA0 += __shfl_xor_sync(0xffffffffu, cA0, m);
        cA1 += __shfl_xor_sync(0xffffffffu, cA1, m);
        cB0 += __shfl_xor_sync(0xffffffffu, cB0, m);
        cB1 += __shfl_xor_sync(0xffffffffu, cB1, m);
    }
    if (lane < 4) {
        atomicAdd(&s_cs[c00], cA0);
        atomicAdd(&s_cs[c00 + 1], cA1);
        atomicAdd(&s_cs[c10], cB0);
        atomicAdd(&s_cs[c10 + 1], cB1);
    }
    __syncthreads();

    // publish block partial colsums (transposed: [col][block])
    if (t < NC) g_partT[t * NBLK + blockIdx.x] = s_cs[t];
    __threadfence();
    __syncthreads();

    // ---- grid sync: all 256 blocks resident (2/SM), epoch ticket ----
    if (t == 0) {
        unsigned ticket;
        asm volatile("atom.global.add.release.gpu.u32 %0, [%1], 1;"
                     : "=r"(ticket) : "l"(&g_arrive) : "memory");
        const unsigned target = (ticket / NBLK + 1u) * NBLK;
        unsigned v;
        do {
            asm volatile("ld.global.acquire.gpu.u32 %0, [%1];"
                         : "=r"(v) : "l"(&g_arrive) : "memory");
        } while (v < target);
    }
    __syncthreads();
    __threadfence();

    // total column sums -> reciprocals: 4 segments x 64 contiguous floats/col
    {
        const int col = t >> 2, seg = t & 3;
        const float4* p4 = (const float4*)(g_partT + col * NBLK + seg * 64);
        float4 acc = __ldcg(p4);
        #pragma unroll 4
        for (int j = 1; j < 16; j++) {
            float4 u = __ldcg(p4 + j);
            acc.x += u.x; acc.y += u.y; acc.z += u.z; acc.w += u.w;
        }
        float s = (acc.x + acc.y) + (acc.z + acc.w);
        s += __shfl_xor_sync(0xffffffffu, s, 1);
        s += __shfl_xor_sync(0xffffffffu, s, 2);
        if (seg == 0) s_ct[col] = frcp_ap(s);
    }
    __syncthreads();

    // ---- Phase 4: P from in-register Q ----
    const float icA0 = s_ct[c00], icA1 = s_ct[c00 + 1];
    const float icB0 = s_ct[c10], icB1 = s_ct[c10 + 1];

    float p00 = q00 * q00 * icA0, p01 = q01 * q01 * icA1;
    float p02 = q02 * q02 * icA0, p03 = q03 * q03 * icA1;
    float p10 = q10 * q10 * icB0, p11 = q11 * q11 * icB1;
    float p12 = q12 * q12 * icB0, p13 = q13 * q13 * icB1;

    float ps0 = (p00 + p01) + (p10 + p11);
    float ps1 = (p02 + p03) + (p12 + p13);
    ps0 += __shfl_xor_sync(0xffffffffu, ps0, 1);
    ps0 += __shfl_xor_sync(0xffffffffu, ps0, 2);
    ps1 += __shfl_xor_sync(0xffffffffu, ps1, 1);
    ps1 += __shfl_xor_sync(0xffffffffu, ps1, 2);
    if (tig == 0) { atomicAdd(&s_pr[R0], ps0); atomicAdd(&s_pr[R1], ps1); }
    __syncthreads();

    const float ip0 = frcp_ap(s_pr[R0]), ip1 = frcp_ap(s_pr[R1]);
    *(float2*)(P + (size_t)gA * NC + c00) = make_float2(p00 * ip0, p01 * ip0);
    *(float2*)(P + (size_t)gB * NC + c00) = make_float2(p02 * ip1, p03 * ip1);
    *(float2*)(P + (size_t)gA * NC + c10) = make_float2(p10 * ip0, p11 * ip0);
    *(float2*)(P + (size_t)gB * NC + c10) = make_float2(p12 * ip1, p13 * ip1);
}

extern "C" void kernel_launch(void* const* d_in, const int* in_sizes, int n_in,
                              void* d_out, int out_size) {
    const float* z    = (const float*)d_in[0];   // (8192, 256) f32
    const float* cent = (const float*)d_in[1];   // (64, 256)   f32
    float* Q = (float*)d_out;
    float* P = Q + (size_t)NR * NC;

    cudaFuncSetAttribute(fused_kernel, cudaFuncAttributeMaxDynamicSharedMemorySize, SMEM_B);
    fused_kernel<<<NBLK, TPB, SMEM_B>>>(z, cent, Q, P);
}

// round 10
// speedup vs baseline: 1.3880x; 1.3880x over previous
#include <cuda_runtime.h>
#include <cuda_bf16.h>
#include <math.h>

#define NR   8192     // rows of z
#define HD   256      // feature dim
#define NC   64       // clusters
#define RPB  64       // rows per block
#define TPB  512      // 16 warps: 4 warp_m x 4 warp_n, warp tile m16n16
#define NBLK (NR / RPB)   // 128 blocks, one wave, 1 block/SM

// bf16 tiles [64][256], row stride 512B, XOR-swizzled; 32KB each
#define OFF_Z  0
#define OFF_C  32768
#define SMEM_B 65536

__device__ float g_partT[NC * NBLK];  // transposed partial colsums [col][block]
__device__ float g_inv[NC];           // broadcast reciprocals of colsums
__device__ unsigned int g_arrive;     // ticket counter (static zero-init)
__device__ unsigned int g_flag;       // epoch flag     (static zero-init)

#define LDSM4(r, addr) \
    asm volatile("ldmatrix.sync.aligned.m8n8.x4.shared.b16 {%0,%1,%2,%3}, [%4];" \
        : "=r"((r)[0]), "=r"((r)[1]), "=r"((r)[2]), "=r"((r)[3]) : "r"(addr))

#define MMA16816(d, a, b0, b1) \
    asm volatile("mma.sync.aligned.m16n8k16.row.col.f32.bf16.bf16.f32 " \
        "{%0,%1,%2,%3},{%4,%5,%6,%7},{%8,%9},{%0,%1,%2,%3};" \
        : "+f"((d)[0]), "+f"((d)[1]), "+f"((d)[2]), "+f"((d)[3]) \
        : "r"((a)[0]), "r"((a)[1]), "r"((a)[2]), "r"((a)[3]), "r"(b0), "r"(b1))

__device__ __forceinline__ unsigned bf2_bits(__nv_bfloat162 h) {
    return *reinterpret_cast<unsigned*>(&h);
}
__device__ __forceinline__ float fsqrt_ap(float x) {
    float r; asm("sqrt.approx.ftz.f32 %0, %1;" : "=f"(r) : "f"(x)); return r;
}
__device__ __forceinline__ float frcp_ap(float x) {
    float r; asm("rcp.approx.ftz.f32 %0, %1;" : "=f"(r) : "f"(x)); return r;
}

// fp32 LDG -> norm in regs -> bf16 pack -> swizzled STS. 8 lanes/row, 64 rows.
__device__ __forceinline__ void convert_rows(const float4* __restrict__ g4,
                                             char* dst, float* norm_out, int t) {
    const int row = t >> 3;
    const int l8 = t & 7;
    float4 v[8];
    #pragma unroll
    for (int j = 0; j < 8; j++) v[j] = g4[row * (HD / 4) + (l8 + 8 * j)];
    float acc = 0.f;
    #pragma unroll
    for (int j = 0; j < 8; j++) {
        const int c4 = l8 + 8 * j;
        acc = fmaf(v[j].x, v[j].x, acc);
        acc = fmaf(v[j].y, v[j].y, acc);
        acc = fmaf(v[j].z, v[j].z, acc);
        acc = fmaf(v[j].w, v[j].w, acc);
        __nv_bfloat162 h01 = __floats2bfloat162_rn(v[j].x, v[j].y);
        __nv_bfloat162 h23 = __floats2bfloat162_rn(v[j].z, v[j].w);
        const int byteoff = 8 * c4;
        const unsigned off = row * 512 +
            ((((byteoff >> 4) ^ (row & 7)) << 4) | (byteoff & 15));
        *(uint2*)(dst + off) = make_uint2(bf2_bits(h01), bf2_bits(h23));
    }
    acc += __shfl_xor_sync(0xffffffffu, acc, 1);
    acc += __shfl_xor_sync(0xffffffffu, acc, 2);
    acc += __shfl_xor_sync(0xffffffffu, acc, 4);
    if (l8 == 0) norm_out[row] = acc;
}

__global__ void __launch_bounds__(TPB, 1)
fused_kernel(const float* __restrict__ z, const float* __restrict__ cent,
             float* __restrict__ Q, float* __restrict__ P) {
    extern __shared__ char smem[];
    char* zt = smem + OFF_Z;
    char* ct = smem + OFF_C;
    __shared__ float s_zn[RPB], s_cn[NC];
    __shared__ float s_rs[RPB], s_cs[NC], s_pr[RPB];
    __shared__ unsigned s_ticket;

    const int t = threadIdx.x;
    const unsigned sb = (unsigned)__cvta_generic_to_shared(smem);

    if (t < NC) s_cs[t] = 0.f;
    if (t < RPB) { s_rs[t] = 0.f; s_pr[t] = 0.f; }

    // ---- Phase 1: load + convert z tile and centroids (norms in registers) ----
    convert_rows((const float4*)(z + (size_t)blockIdx.x * RPB * HD), zt, s_zn, t);
    convert_rows((const float4*)cent, ct, s_cn, t);
    __syncthreads();

    // ---- Phase 2: bf16 GEMM mainloop (single-term), warp m16n16, k16/step ----
    const int lane = t & 31, wid = t >> 5;
    const int wm = wid >> 2, wn = wid & 3;
    const int tile = lane >> 3, rit = lane & 7;

    const int arow = wm * 16 + rit + 8 * (tile & 1);
    const int acb = tile >> 1;
    const unsigned abase = sb + OFF_Z + arow * 512;
    const int axor = arow & 7;

    const int brow = wn * 16 + rit + 8 * (tile >> 1);
    const int bcb = tile & 1;
    const unsigned bbase = sb + OFF_C + brow * 512;
    const int bxor = brow & 7;

    float d0[4] = {0.f, 0.f, 0.f, 0.f};   // n-half 0
    float d1[4] = {0.f, 0.f, 0.f, 0.f};   // n-half 1

    #pragma unroll
    for (int ks = 0; ks < 16; ks++) {
        const unsigned aoff = (unsigned)(((2 * ks + acb) ^ axor) << 4);
        const unsigned boff = (unsigned)(((2 * ks + bcb) ^ bxor) << 4);
        unsigned a[4], b[4];
        LDSM4(a, abase + aoff);
        LDSM4(b, bbase + boff);
        MMA16816(d0, a, b[0], b[1]);
        MMA16816(d1, a, b[2], b[3]);
    }

    // ---- Phase 3: epilogue -> Q ----
    const int gid = lane >> 2, tig = lane & 3;
    const int R0 = wm * 16 + gid, R1 = R0 + 8;
    const float znA = s_zn[R0], znB = s_zn[R1];
    const int c00 = wn * 16 + 2 * tig;
    const int c10 = c00 + 8;
    const float cnA0 = s_cn[c00], cnA1 = s_cn[c00 + 1];
    const float cnB0 = s_cn[c10], cnB1 = s_cn[c10 + 1];

    float q00 = frcp_ap(1.f + fsqrt_ap(fmaxf(fmaf(-2.f, d0[0], znA + cnA0), 0.f)));
    float q01 = frcp_ap(1.f + fsqrt_ap(fmaxf(fmaf(-2.f, d0[1], znA + cnA1), 0.f)));
    float q02 = frcp_ap(1.f + fsqrt_ap(fmaxf(fmaf(-2.f, d0[2], znB + cnA0), 0.f)));
    float q03 = frcp_ap(1.f + fsqrt_ap(fmaxf(fmaf(-2.f, d0[3], znB + cnA1), 0.f)));
    float q10 = frcp_ap(1.f + fsqrt_ap(fmaxf(fmaf(-2.f, d1[0], znA + cnB0), 0.f)));
    float q11 = frcp_ap(1.f + fsqrt_ap(fmaxf(fmaf(-2.f, d1[1], znA + cnB1), 0.f)));
    float q12 = frcp_ap(1.f + fsqrt_ap(fmaxf(fmaf(-2.f, d1[2], znB + cnB0), 0.f)));
    float q13 = frcp_ap(1.f + fsqrt_ap(fmaxf(fmaf(-2.f, d1[3], znB + cnB1), 0.f)));

    float rs0 = (q00 + q01) + (q10 + q11);
    float rs1 = (q02 + q03) + (q12 + q13);
    rs0 += __shfl_xor_sync(0xffffffffu, rs0, 1);
    rs0 += __shfl_xor_sync(0xffffffffu, rs0, 2);
    rs1 += __shfl_xor_sync(0xffffffffu, rs1, 1);
    rs1 += __shfl_xor_sync(0xffffffffu, rs1, 2);
    if (tig == 0) { atomicAdd(&s_rs[R0], rs0); atomicAdd(&s_rs[R1], rs1); }
    __syncthreads();

    const float ir0 = frcp_ap(s_rs[R0]), ir1 = frcp_ap(s_rs[R1]);
    q00 *= ir0; q01 *= ir0; q10 *= ir0; q11 *= ir0;
    q02 *= ir1; q03 *= ir1; q12 *= ir1; q13 *= ir1;

    const int gA = blockIdx.x * RPB + R0;
    const int gB = blockIdx.x * RPB + R1;
    *(float2*)(Q + (size_t)gA * NC + c00) = make_float2(q00, q01);
    *(float2*)(Q + (size_t)gB * NC + c00) = make_float2(q02, q03);
    *(float2*)(Q + (size_t)gA * NC + c10) = make_float2(q10, q11);
    *(float2*)(Q + (size_t)gB * NC + c10) = make_float2(q12, q13);

    float cA0 = q00 + q02, cA1 = q01 + q03;
    float cB0 = q10 + q12, cB1 = q11 + q13;
    #pragma unroll
    for (int m = 4; m <= 16; m <<= 1) {
        cA0 += __shfl_xor_sync(0xffffffffu, cA0, m);
        cA1 += __shfl_xor_sync(0xffffffffu, cA1, m);
        cB0 += __shfl_xor_sync(0xffffffffu, cB0, m);
        cB1 += __shfl_xor_sync(0xffffffffu, cB1, m);
    }
    if (lane < 4) {
        atomicAdd(&s_cs[c00], cA0);
        atomicAdd(&s_cs[c00 + 1], cA1);
        atomicAdd(&s_cs[c10], cB0);
        atomicAdd(&s_cs[c10 + 1], cB1);
    }
    __syncthreads();

    // publish block partial colsums (transposed: [col][block])
    if (t < NC) g_partT[t * NBLK + blockIdx.x] = s_cs[t];
    __threadfence();
    __syncthreads();

    // ---- arrival ticket; LAST arriver gathers + broadcasts reciprocals ----
    if (t == 0) {
        unsigned ticket;
        asm volatile("atom.acq_rel.gpu.global.add.u32 %0, [%1], 1;"
                     : "=r"(ticket) : "l"(&g_arrive) : "memory");
        s_ticket = ticket;
    }
    __syncthreads();
    const unsigned ticket = s_ticket;
    const unsigned epoch = ticket / NBLK + 1u;

    if (ticket % NBLK == NBLK - 1u) {
        // gatherer block: 8 segments x 16 floats per column
        const int col = t >> 3, seg = t & 7;
        const float4* p4 = (const float4*)(g_partT + col * NBLK + seg * 16);
        float4 u = __ldcg(p4);
        float4 w = __ldcg(p4 + 1);
        float4 x = __ldcg(p4 + 2);
        float4 y = __ldcg(p4 + 3);
        float s = (((u.x + u.y) + (u.z + u.w)) + ((w.x + w.y) + (w.z + w.w)))
                + (((x.x + x.y) + (x.z + x.w)) + ((y.x + y.y) + (y.z + y.w)));
        s += __shfl_xor_sync(0xffffffffu, s, 1);
        s += __shfl_xor_sync(0xffffffffu, s, 2);
        s += __shfl_xor_sync(0xffffffffu, s, 4);
        if (seg == 0) g_inv[col] = frcp_ap(s);
        __threadfence();
        __syncthreads();
        if (t == 0)
            asm volatile("st.release.gpu.global.u32 [%0], %1;"
                         :: "l"(&g_flag), "r"(epoch) : "memory");
    }

    // everyone (incl. gatherer, where it passes immediately) waits for epoch
    if (t == 0) {
        unsigned v;
        do {
            asm volatile("ld.global.acquire.gpu.u32 %0, [%1];"
                         : "=r"(v) : "l"(&g_flag) : "memory");
        } while (v < epoch);
    }
    __syncthreads();

    // ---- Phase 4: P from in-register Q (reciprocals direct from L2) ----
    const float icA0 = __ldcg(&g_inv[c00]), icA1 = __ldcg(&g_inv[c00 + 1]);
    const float icB0 = __ldcg(&g_inv[c10]), icB1 = __ldcg(&g_inv[c10 + 1]);

    float p00 = q00 * q00 * icA0, p01 = q01 * q01 * icA1;
    float p02 = q02 * q02 * icA0, p03 = q03 * q03 * icA1;
    float p10 = q10 * q10 * icB0, p11 = q11 * q11 * icB1;
    float p12 = q12 * q12 * icB0, p13 = q13 * q13 * icB1;

    float ps0 = (p00 + p01) + (p10 + p11);
    float ps1 = (p02 + p03) + (p12 + p13);
    ps0 += __shfl_xor_sync(0xffffffffu, ps0, 1);
    ps0 += __shfl_xor_sync(0xffffffffu, ps0, 2);
    ps1 += __shfl_xor_sync(0xffffffffu, ps1, 1);
    ps1 += __shfl_xor_sync(0xffffffffu, ps1, 2);
    if (tig == 0) { atomicAdd(&s_pr[R0], ps0); atomicAdd(&s_pr[R1], ps1); }
    __syncthreads();

    const float ip0 = frcp_ap(s_pr[R0]), ip1 = frcp_ap(s_pr[R1]);
    *(float2*)(P + (size_t)gA * NC + c00) = make_float2(p00 * ip0, p01 * ip0);
    *(float2*)(P + (size_t)gB * NC + c00) = make_float2(p02 * ip1, p03 * ip1);
    *(float2*)(P + (size_t)gA * NC + c10) = make_float2(p10 * ip0, p11 * ip0);
    *(float2*)(P + (size_t)gB * NC + c10) = make_float2(p12 * ip1, p13 * ip1);
}

extern "C" void kernel_launch(void* const* d_in, const int* in_sizes, int n_in,
                              void* d_out, int out_size) {
    const float* z    = (const float*)d_in[0];   // (8192, 256) f32
    const float* cent = (const float*)d_in[1];   // (64, 256)   f32
    float* Q = (float*)d_out;
    float* P = Q + (size_t)NR * NC;

    cudaFuncSetAttribute(fused_kernel, cudaFuncAttributeMaxDynamicSharedMemorySize, SMEM_B);
    fused_kernel<<<NBLK, TPB, SMEM_B>>>(z, cent, Q, P);
}

// round 11
// speedup vs baseline: 1.7666x; 1.2727x over previous
#include <cuda_runtime.h>
#include <cuda_bf16.h>
#include <math.h>

#define NR   8192     // rows of z
#define HD   256      // feature dim
#define NC   64       // clusters
#define RPB  64       // rows per block
#define TPB  512      // 16 warps: 4 warp_m x 4 warp_n, warp tile m16n16
#define NBLK (NR / RPB)   // 128 blocks, one wave, 1 block/SM

// bf16 tiles [64][256], row stride 512B, XOR-swizzled; 32KB each
#define OFF_Z  0
#define OFF_C  32768
#define SMEM_B 65536

__device__ float g_partT[NC * NBLK];  // transposed partial colsums [col][block]
__device__ unsigned int g_arrive;     // epoch ticket counter (static zero-init)

#define LDSM4(r, addr) \
    asm volatile("ldmatrix.sync.aligned.m8n8.x4.shared.b16 {%0,%1,%2,%3}, [%4];" \
        : "=r"((r)[0]), "=r"((r)[1]), "=r"((r)[2]), "=r"((r)[3]) : "r"(addr))

#define MMA16816(d, a, b0, b1) \
    asm volatile("mma.sync.aligned.m16n8k16.row.col.f32.bf16.bf16.f32 " \
        "{%0,%1,%2,%3},{%4,%5,%6,%7},{%8,%9},{%0,%1,%2,%3};" \
        : "+f"((d)[0]), "+f"((d)[1]), "+f"((d)[2]), "+f"((d)[3]) \
        : "r"((a)[0]), "r"((a)[1]), "r"((a)[2]), "r"((a)[3]), "r"(b0), "r"(b1))

__device__ __forceinline__ unsigned bf2_bits(__nv_bfloat162 h) {
    return *reinterpret_cast<unsigned*>(&h);
}
__device__ __forceinline__ float fsqrt_ap(float x) {
    float r; asm("sqrt.approx.ftz.f32 %0, %1;" : "=f"(r) : "f"(x)); return r;
}
__device__ __forceinline__ float frcp_ap(float x) {
    float r; asm("rcp.approx.ftz.f32 %0, %1;" : "=f"(r) : "f"(x)); return r;
}

// fp32 LDG -> norm in regs -> bf16 pack -> swizzled STS. 8 lanes/row, 64 rows.
__device__ __forceinline__ void convert_rows(const float4* __restrict__ g4,
                                             char* dst, float* norm_out, int t) {
    const int row = t >> 3;
    const int l8 = t & 7;
    float4 v[8];
    #pragma unroll
    for (int j = 0; j < 8; j++) v[j] = g4[row * (HD / 4) + (l8 + 8 * j)];
    float acc = 0.f;
    #pragma unroll
    for (int j = 0; j < 8; j++) {
        const int c4 = l8 + 8 * j;
        acc = fmaf(v[j].x, v[j].x, acc);
        acc = fmaf(v[j].y, v[j].y, acc);
        acc = fmaf(v[j].z, v[j].z, acc);
        acc = fmaf(v[j].w, v[j].w, acc);
        __nv_bfloat162 h01 = __floats2bfloat162_rn(v[j].x, v[j].y);
        __nv_bfloat162 h23 = __floats2bfloat162_rn(v[j].z, v[j].w);
        const int byteoff = 8 * c4;
        const unsigned off = row * 512 +
            ((((byteoff >> 4) ^ (row & 7)) << 4) | (byteoff & 15));
        *(uint2*)(dst + off) = make_uint2(bf2_bits(h01), bf2_bits(h23));
    }
    acc += __shfl_xor_sync(0xffffffffu, acc, 1);
    acc += __shfl_xor_sync(0xffffffffu, acc, 2);
    acc += __shfl_xor_sync(0xffffffffu, acc, 4);
    if (l8 == 0) norm_out[row] = acc;
}

__global__ void __launch_bounds__(TPB, 1)
fused_kernel(const float* __restrict__ z, const float* __restrict__ cent,
             float* __restrict__ Q, float* __restrict__ P) {
    extern __shared__ char smem[];
    char* zt = smem + OFF_Z;
    char* ct = smem + OFF_C;
    __shared__ float s_zn[RPB], s_cn[NC];
    __shared__ float s_rs[RPB], s_cs[NC], s_ct[NC], s_pr[RPB];

    const int t = threadIdx.x;
    const unsigned sb = (unsigned)__cvta_generic_to_shared(smem);

    if (t < NC) { s_cs[t] = 0.f; s_ct[t] = 0.f; }
    if (t < RPB) { s_rs[t] = 0.f; s_pr[t] = 0.f; }

    // ---- Phase 1: load + convert z tile and centroids (norms in registers) ----
    convert_rows((const float4*)(z + (size_t)blockIdx.x * RPB * HD), zt, s_zn, t);
    convert_rows((const float4*)cent, ct, s_cn, t);
    __syncthreads();

    // ---- Phase 2: bf16 GEMM mainloop (single-term), warp m16n16, k16/step ----
    const int lane = t & 31, wid = t >> 5;
    const int wm = wid >> 2, wn = wid & 3;
    const int tile = lane >> 3, rit = lane & 7;

    const int arow = wm * 16 + rit + 8 * (tile & 1);
    const int acb = tile >> 1;
    const unsigned abase = sb + OFF_Z + arow * 512;
    const int axor = arow & 7;

    const int brow = wn * 16 + rit + 8 * (tile >> 1);
    const int bcb = tile & 1;
    const unsigned bbase = sb + OFF_C + brow * 512;
    const int bxor = brow & 7;

    float d0[4] = {0.f, 0.f, 0.f, 0.f};   // n-half 0
    float d1[4] = {0.f, 0.f, 0.f, 0.f};   // n-half 1

    #pragma unroll
    for (int ks = 0; ks < 16; ks++) {
        const unsigned aoff = (unsigned)(((2 * ks + acb) ^ axor) << 4);
        const unsigned boff = (unsigned)(((2 * ks + bcb) ^ bxor) << 4);
        unsigned a[4], b[4];
        LDSM4(a, abase + aoff);
        LDSM4(b, bbase + boff);
        MMA16816(d0, a, b[0], b[1]);
        MMA16816(d1, a, b[2], b[3]);
    }

    // ---- Phase 3: epilogue -> Q ----
    const int gid = lane >> 2, tig = lane & 3;
    const int R0 = wm * 16 + gid, R1 = R0 + 8;
    const float znA = s_zn[R0], znB = s_zn[R1];
    const int c00 = wn * 16 + 2 * tig;
    const int c10 = c00 + 8;
    const float cnA0 = s_cn[c00], cnA1 = s_cn[c00 + 1];
    const float cnB0 = s_cn[c10], cnB1 = s_cn[c10 + 1];

    float q00 = frcp_ap(1.f + fsqrt_ap(fmaxf(fmaf(-2.f, d0[0], znA + cnA0), 0.f)));
    float q01 = frcp_ap(1.f + fsqrt_ap(fmaxf(fmaf(-2.f, d0[1], znA + cnA1), 0.f)));
    float q02 = frcp_ap(1.f + fsqrt_ap(fmaxf(fmaf(-2.f, d0[2], znB + cnA0), 0.f)));
    float q03 = frcp_ap(1.f + fsqrt_ap(fmaxf(fmaf(-2.f, d0[3], znB + cnA1), 0.f)));
    float q10 = frcp_ap(1.f + fsqrt_ap(fmaxf(fmaf(-2.f, d1[0], znA + cnB0), 0.f)));
    float q11 = frcp_ap(1.f + fsqrt_ap(fmaxf(fmaf(-2.f, d1[1], znA + cnB1), 0.f)));
    float q12 = frcp_ap(1.f + fsqrt_ap(fmaxf(fmaf(-2.f, d1[2], znB + cnB0), 0.f)));
    float q13 = frcp_ap(1.f + fsqrt_ap(fmaxf(fmaf(-2.f, d1[3], znB + cnB1), 0.f)));

    float rs0 = (q00 + q01) + (q10 + q11);
    float rs1 = (q02 + q03) + (q12 + q13);
    rs0 += __shfl_xor_sync(0xffffffffu, rs0, 1);
    rs0 += __shfl_xor_sync(0xffffffffu, rs0, 2);
    rs1 += __shfl_xor_sync(0xffffffffu, rs1, 1);
    rs1 += __shfl_xor_sync(0xffffffffu, rs1, 2);
    if (tig == 0) { atomicAdd(&s_rs[R0], rs0); atomicAdd(&s_rs[R1], rs1); }
    __syncthreads();

    const float ir0 = frcp_ap(s_rs[R0]), ir1 = frcp_ap(s_rs[R1]);
    q00 *= ir0; q01 *= ir0; q10 *= ir0; q11 *= ir0;
    q02 *= ir1; q03 *= ir1; q12 *= ir1; q13 *= ir1;

    const int gA = blockIdx.x * RPB + R0;
    const int gB = blockIdx.x * RPB + R1;
    *(float2*)(Q + (size_t)gA * NC + c00) = make_float2(q00, q01);
    *(float2*)(Q + (size_t)gB * NC + c00) = make_float2(q02, q03);
    *(float2*)(Q + (size_t)gA * NC + c10) = make_float2(q10, q11);
    *(float2*)(Q + (size_t)gB * NC + c10) = make_float2(q12, q13);

    float cA0 = q00 + q02, cA1 = q01 + q03;
    float cB0 = q10 + q12, cB1 = q11 + q13;
    #pragma unroll
    for (int m = 4; m <= 16; m <<= 1) {
        cA0 += __shfl_xor_sync(0xffffffffu, cA0, m);
        cA1 += __shfl_xor_sync(0xffffffffu, cA1, m);
        cB0 += __shfl_xor_sync(0xffffffffu, cB0, m);
        cB1 += __shfl_xor_sync(0xffffffffu, cB1, m);
    }
    if (lane < 4) {
        atomicAdd(&s_cs[c00], cA0);
        atomicAdd(&s_cs[c00 + 1], cA1);
        atomicAdd(&s_cs[c10], cB0);
        atomicAdd(&s_cs[c10 + 1], cB1);
    }
    __syncthreads();

    // publish block partial colsums (transposed: [col][block])
    if (t < NC) g_partT[t * NBLK + blockIdx.x] = s_cs[t];
    __threadfence();
    __syncthreads();

    // ---- single-wave grid sync (epoch ticket; replay-deterministic) ----
    if (t == 0) {
        unsigned ticket;
        asm volatile("atom.global.add.release.gpu.u32 %0, [%1], 1;"
                     : "=r"(ticket) : "l"(&g_arrive) : "memory");
        const unsigned target = (ticket / NBLK + 1u) * NBLK;
        unsigned v;
        do {
            asm volatile("ld.global.acquire.gpu.u32 %0, [%1];"
                         : "=r"(v) : "l"(&g_arrive) : "memory");
        } while (v < target);
    }
    __syncthreads();
    __threadfence();

    // total column sums (parallel per-block gather): 8 seg x 16 floats/col
    {
        const int col = t >> 3, seg = t & 7;
        const float4* p4 = (const float4*)(g_partT + col * NBLK + seg * 16);
        float4 u = __ldcg(p4);
        float4 w = __ldcg(p4 + 1);
        float4 x = __ldcg(p4 + 2);
        float4 y = __ldcg(p4 + 3);
        float s = (((u.x + u.y) + (u.z + u.w)) + ((w.x + w.y) + (w.z + w.w)))
                + (((x.x + x.y) + (x.z + x.w)) + ((y.x + y.y) + (y.z + y.w)));
        s += __shfl_xor_sync(0xffffffffu, s, 1);
        s += __shfl_xor_sync(0xffffffffu, s, 2);
        s += __shfl_xor_sync(0xffffffffu, s, 4);
        if (seg == 0) s_ct[col] = frcp_ap(s);
    }
    __syncthreads();

    // ---- Phase 4: P from in-register Q ----
    const float icA0 = s_ct[c00], icA1 = s_ct[c00 + 1];
    const float icB0 = s_ct[c10], icB1 = s_ct[c10 + 1];

    float p00 = q00 * q00 * icA0, p01 = q01 * q01 * icA1;
    float p02 = q02 * q02 * icA0, p03 = q03 * q03 * icA1;
    float p10 = q10 * q10 * icB0, p11 = q11 * q11 * icB1;
    float p12 = q12 * q12 * icB0, p13 = q13 * q13 * icB1;

    float ps0 = (p00 + p01) + (p10 + p11);
    float ps1 = (p02 + p03) + (p12 + p13);
    ps0 += __shfl_xor_sync(0xffffffffu, ps0, 1);
    ps0 += __shfl_xor_sync(0xffffffffu, ps0, 2);
    ps1 += __shfl_xor_sync(0xffffffffu, ps1, 1);
    ps1 += __shfl_xor_sync(0xffffffffu, ps1, 2);
    if (tig == 0) { atomicAdd(&s_pr[R0], ps0); atomicAdd(&s_pr[R1], ps1); }
    __syncthreads();

    const float ip0 = frcp_ap(s_pr[R0]), ip1 = frcp_ap(s_pr[R1]);
    *(float2*)(P + (size_t)gA * NC + c00) = make_float2(p00 * ip0, p01 * ip0);
    *(float2*)(P + (size_t)gB * NC + c00) = make_float2(p02 * ip1, p03 * ip1);
    *(float2*)(P + (size_t)gA * NC + c10) = make_float2(p10 * ip0, p11 * ip0);
    *(float2*)(P + (size_t)gB * NC + c10) = make_float2(p12 * ip1, p13 * ip1);
}

extern "C" void kernel_launch(void* const* d_in, const int* in_sizes, int n_in,
                              void* d_out, int out_size) {
    const float* z    = (const float*)d_in[0];   // (8192, 256) f32
    const float* cent = (const float*)d_in[1];   // (64, 256)   f32
    float* Q = (float*)d_out;
    float* P = Q + (size_t)NR * NC;

    cudaFuncSetAttribute(fused_kernel, cudaFuncAttributeMaxDynamicSharedMemorySize, SMEM_B);
    fused_kernel<<<NBLK, TPB, SMEM_B>>>(z, cent, Q, P);
}

// round 12
// speedup vs baseline: 1.7975x; 1.0175x over previous
#include <cuda_runtime.h>
#include <cuda_bf16.h>
#include <math.h>

#define NR   8192     // rows of z
#define HD   256      // feature dim
#define NC   64       // clusters
#define RPB  64       // rows per block
#define TPB  512      // 16 warps: 4 warp_m x 4 warp_n, warp tile m16n16
#define NBLK (NR / RPB)   // 128 blocks, one wave, 1 block/SM

// bf16 tiles [64][256], row stride 512B, XOR-swizzled; 32KB each
#define OFF_Z  0
#define OFF_C  32768
#define SMEM_B 65536

__device__ float g_partT[NC * NBLK];  // transposed partial colsums [col][block]
__device__ unsigned int g_arrive;     // epoch ticket counter (static zero-init)

#define LDSM4(r, addr) \
    asm volatile("ldmatrix.sync.aligned.m8n8.x4.shared.b16 {%0,%1,%2,%3}, [%4];" \
        : "=r"((r)[0]), "=r"((r)[1]), "=r"((r)[2]), "=r"((r)[3]) : "r"(addr))

#define MMA16816(d, a, b0, b1) \
    asm volatile("mma.sync.aligned.m16n8k16.row.col.f32.bf16.bf16.f32 " \
        "{%0,%1,%2,%3},{%4,%5,%6,%7},{%8,%9},{%0,%1,%2,%3};" \
        : "+f"((d)[0]), "+f"((d)[1]), "+f"((d)[2]), "+f"((d)[3]) \
        : "r"((a)[0]), "r"((a)[1]), "r"((a)[2]), "r"((a)[3]), "r"(b0), "r"(b1))

__device__ __forceinline__ unsigned bf2_bits(__nv_bfloat162 h) {
    return *reinterpret_cast<unsigned*>(&h);
}
__device__ __forceinline__ float fsqrt_ap(float x) {
    float r; asm("sqrt.approx.ftz.f32 %0, %1;" : "=f"(r) : "f"(x)); return r;
}
__device__ __forceinline__ float frcp_ap(float x) {
    float r; asm("rcp.approx.ftz.f32 %0, %1;" : "=f"(r) : "f"(x)); return r;
}

__global__ void __launch_bounds__(TPB, 1)
fused_kernel(const float* __restrict__ z, const float* __restrict__ cent,
             float* __restrict__ Q, float* __restrict__ P) {
    extern __shared__ char smem[];
    char* zt = smem + OFF_Z;
    char* ct = smem + OFF_C;
    __shared__ float s_zn[RPB], s_cn[NC];
    __shared__ float s_rs[RPB], s_cs[NC], s_ct[NC], s_pr[RPB];

    const int t = threadIdx.x;
    const unsigned sb = (unsigned)__cvta_generic_to_shared(smem);

    if (t < NC) { s_cs[t] = 0.f; s_ct[t] = 0.f; }
    if (t < RPB) { s_rs[t] = 0.f; s_pr[t] = 0.f; }

    // ---- Phase 1: issue ALL 16 LDG.128 up front (z + centroids), then convert ----
    {
        const int row = t >> 3;
        const int l8 = t & 7;
        const float4* zg = (const float4*)(z + (size_t)blockIdx.x * RPB * HD);
        const float4* cg = (const float4*)cent;

        float4 vz[8], vc[8];
        #pragma unroll
        for (int j = 0; j < 8; j++) vz[j] = zg[row * (HD / 4) + (l8 + 8 * j)];
        #pragma unroll
        for (int j = 0; j < 8; j++) vc[j] = cg[row * (HD / 4) + (l8 + 8 * j)];

        float az = 0.f, ac = 0.f;
        #pragma unroll
        for (int j = 0; j < 8; j++) {
            const int c4 = l8 + 8 * j;
            const int byteoff = 8 * c4;
            const unsigned off = row * 512 +
                ((((byteoff >> 4) ^ (row & 7)) << 4) | (byteoff & 15));

            az = fmaf(vz[j].x, vz[j].x, az);
            az = fmaf(vz[j].y, vz[j].y, az);
            az = fmaf(vz[j].z, vz[j].z, az);
            az = fmaf(vz[j].w, vz[j].w, az);
            __nv_bfloat162 zh01 = __floats2bfloat162_rn(vz[j].x, vz[j].y);
            __nv_bfloat162 zh23 = __floats2bfloat162_rn(vz[j].z, vz[j].w);
            *(uint2*)(zt + off) = make_uint2(bf2_bits(zh01), bf2_bits(zh23));

            ac = fmaf(vc[j].x, vc[j].x, ac);
            ac = fmaf(vc[j].y, vc[j].y, ac);
            ac = fmaf(vc[j].z, vc[j].z, ac);
            ac = fmaf(vc[j].w, vc[j].w, ac);
            __nv_bfloat162 ch01 = __floats2bfloat162_rn(vc[j].x, vc[j].y);
            __nv_bfloat162 ch23 = __floats2bfloat162_rn(vc[j].z, vc[j].w);
            *(uint2*)(ct + off) = make_uint2(bf2_bits(ch01), bf2_bits(ch23));
        }
        az += __shfl_xor_sync(0xffffffffu, az, 1);
        az += __shfl_xor_sync(0xffffffffu, az, 2);
        az += __shfl_xor_sync(0xffffffffu, az, 4);
        ac += __shfl_xor_sync(0xffffffffu, ac, 1);
        ac += __shfl_xor_sync(0xffffffffu, ac, 2);
        ac += __shfl_xor_sync(0xffffffffu, ac, 4);
        if (l8 == 0) { s_zn[row] = az; s_cn[row] = ac; }
    }
    __syncthreads();

    // ---- Phase 2: bf16 GEMM mainloop (single-term), warp m16n16, k16/step ----
    const int lane = t & 31, wid = t >> 5;
    const int wm = wid >> 2, wn = wid & 3;
    const int tile = lane >> 3, rit = lane & 7;

    const int arow = wm * 16 + rit + 8 * (tile & 1);
    const int acb = tile >> 1;
    const unsigned abase = sb + OFF_Z + arow * 512;
    const int axor = arow & 7;

    const int brow = wn * 16 + rit + 8 * (tile >> 1);
    const int bcb = tile & 1;
    const unsigned bbase = sb + OFF_C + brow * 512;
    const int bxor = brow & 7;

    float d0[4] = {0.f, 0.f, 0.f, 0.f};   // n-half 0
    float d1[4] = {0.f, 0.f, 0.f, 0.f};   // n-half 1

    #pragma unroll
    for (int ks = 0; ks < 16; ks++) {
        const unsigned aoff = (unsigned)(((2 * ks + acb) ^ axor) << 4);
        const unsigned boff = (unsigned)(((2 * ks + bcb) ^ bxor) << 4);
        unsigned a[4], b[4];
        LDSM4(a, abase + aoff);
        LDSM4(b, bbase + boff);
        MMA16816(d0, a, b[0], b[1]);
        MMA16816(d1, a, b[2], b[3]);
    }

    // ---- Phase 3: epilogue -> Q ----
    const int gid = lane >> 2, tig = lane & 3;
    const int R0 = wm * 16 + gid, R1 = R0 + 8;
    const float znA = s_zn[R0], znB = s_zn[R1];
    const int c00 = wn * 16 + 2 * tig;
    const int c10 = c00 + 8;
    const float cnA0 = s_cn[c00], cnA1 = s_cn[c00 + 1];
    const float cnB0 = s_cn[c10], cnB1 = s_cn[c10 + 1];

    float q00 = frcp_ap(1.f + fsqrt_ap(fmaxf(fmaf(-2.f, d0[0], znA + cnA0), 0.f)));
    float q01 = frcp_ap(1.f + fsqrt_ap(fmaxf(fmaf(-2.f, d0[1], znA + cnA1), 0.f)));
    float q02 = frcp_ap(1.f + fsqrt_ap(fmaxf(fmaf(-2.f, d0[2], znB + cnA0), 0.f)));
    float q03 = frcp_ap(1.f + fsqrt_ap(fmaxf(fmaf(-2.f, d0[3], znB + cnA1), 0.f)));
    float q10 = frcp_ap(1.f + fsqrt_ap(fmaxf(fmaf(-2.f, d1[0], znA + cnB0), 0.f)));
    float q11 = frcp_ap(1.f + fsqrt_ap(fmaxf(fmaf(-2.f, d1[1], znA + cnB1), 0.f)));
    float q12 = frcp_ap(1.f + fsqrt_ap(fmaxf(fmaf(-2.f, d1[2], znB + cnB0), 0.f)));
    float q13 = frcp_ap(1.f + fsqrt_ap(fmaxf(fmaf(-2.f, d1[3], znB + cnB1), 0.f)));

    float rs0 = (q00 + q01) + (q10 + q11);
    float rs1 = (q02 + q03) + (q12 + q13);
    rs0 += __shfl_xor_sync(0xffffffffu, rs0, 1);
    rs0 += __shfl_xor_sync(0xffffffffu, rs0, 2);
    rs1 += __shfl_xor_sync(0xffffffffu, rs1, 1);
    rs1 += __shfl_xor_sync(0xffffffffu, rs1, 2);
    if (tig == 0) { atomicAdd(&s_rs[R0], rs0); atomicAdd(&s_rs[R1], rs1); }
    __syncthreads();

    const float ir0 = frcp_ap(s_rs[R0]), ir1 = frcp_ap(s_rs[R1]);
    q00 *= ir0; q01 *= ir0; q10 *= ir0; q11 *= ir0;
    q02 *= ir1; q03 *= ir1; q12 *= ir1; q13 *= ir1;

    const int gA = blockIdx.x * RPB + R0;
    const int gB = blockIdx.x * RPB + R1;
    *(float2*)(Q + (size_t)gA * NC + c00) = make_float2(q00, q01);
    *(float2*)(Q + (size_t)gB * NC + c00) = make_float2(q02, q03);
    *(float2*)(Q + (size_t)gA * NC + c10) = make_float2(q10, q11);
    *(float2*)(Q + (size_t)gB * NC + c10) = make_float2(q12, q13);

    float cA0 = q00 + q02, cA1 = q01 + q03;
    float cB0 = q10 + q12, cB1 = q11 + q13;
    #pragma unroll
    for (int m = 4; m <= 16; m <<= 1) {
        cA0 += __shfl_xor_sync(0xffffffffu, cA0, m);
        cA1 += __shfl_xor_sync(0xffffffffu, cA1, m);
        cB0 += __shfl_xor_sync(0xffffffffu, cB0, m);
        cB1 += __shfl_xor_sync(0xffffffffu, cB1, m);
    }
    if (lane < 4) {
        atomicAdd(&s_cs[c00], cA0);
        atomicAdd(&s_cs[c00 + 1], cA1);
        atomicAdd(&s_cs[c10], cB0);
        atomicAdd(&s_cs[c10 + 1], cB1);
    }
    __syncthreads();

    // publish block partial colsums (transposed: [col][block])
    if (t < NC) g_partT[t * NBLK + blockIdx.x] = s_cs[t];
    __syncthreads();

    // ---- single-wave grid sync (epoch ticket; release/acquire ordering) ----
    if (t == 0) {
        unsigned ticket;
        asm volatile("atom.global.add.release.gpu.u32 %0, [%1], 1;"
                     : "=r"(ticket) : "l"(&g_arrive) : "memory");
        const unsigned target = (ticket / NBLK + 1u) * NBLK;
        unsigned v;
        while (true) {
            asm volatile("ld.global.acquire.gpu.u32 %0, [%1];"
                         : "=r"(v) : "l"(&g_arrive) : "memory");
            if (v >= target) break;
            __nanosleep(64);
        }
    }
    __syncthreads();

    // total column sums (parallel per-block gather): 8 seg x 16 floats/col
    {
        const int col = t >> 3, seg = t & 7;
        const float4* p4 = (const float4*)(g_partT + col * NBLK + seg * 16);
        float4 u = __ldcg(p4);
        float4 w = __ldcg(p4 + 1);
        float4 x = __ldcg(p4 + 2);
        float4 y = __ldcg(p4 + 3);
        float s = (((u.x + u.y) + (u.z + u.w)) + ((w.x + w.y) + (w.z + w.w)))
                + (((x.x + x.y) + (x.z + x.w)) + ((y.x + y.y) + (y.z + y.w)));
        s += __shfl_xor_sync(0xffffffffu, s, 1);
        s += __shfl_xor_sync(0xffffffffu, s, 2);
        s += __shfl_xor_sync(0xffffffffu, s, 4);
        if (seg == 0) s_ct[col] = frcp_ap(s);
    }
    __syncthreads();

    // ---- Phase 4: P from in-register Q ----
    const float icA0 = s_ct[c00], icA1 = s_ct[c00 + 1];
    const float icB0 = s_ct[c10], icB1 = s_ct[c10 + 1];

    float p00 = q00 * q00 * icA0, p01 = q01 * q01 * icA1;
    float p02 = q02 * q02 * icA0, p03 = q03 * q03 * icA1;
    float p10 = q10 * q10 * icB0, p11 = q11 * q11 * icB1;
    float p12 = q12 * q12 * icB0, p13 = q13 * q13 * icB1;

    float ps0 = (p00 + p01) + (p10 + p11);
    float ps1 = (p02 + p03) + (p12 + p13);
    ps0 += __shfl_xor_sync(0xffffffffu, ps0, 1);
    ps0 += __shfl_xor_sync(0xffffffffu, ps0, 2);
    ps1 += __shfl_xor_sync(0xffffffffu, ps1, 1);
    ps1 += __shfl_xor_sync(0xffffffffu, ps1, 2);
    if (tig == 0) { atomicAdd(&s_pr[R0], ps0); atomicAdd(&s_pr[R1], ps1); }
    __syncthreads();

    const float ip0 = frcp_ap(s_pr[R0]), ip1 = frcp_ap(s_pr[R1]);
    *(float2*)(P + (size_t)gA * NC + c00) = make_float2(p00 * ip0, p01 * ip0);
    *(float2*)(P + (size_t)gB * NC + c00) = make_float2(p02 * ip1, p03 * ip1);
    *(float2*)(P + (size_t)gA * NC + c10) = make_float2(p10 * ip0, p11 * ip0);
    *(float2*)(P + (size_t)gB * NC + c10) = make_float2(p12 * ip1, p13 * ip1);
}

extern "C" void kernel_launch(void* const* d_in, const int* in_sizes, int n_in,
                              void* d_out, int out_size) {
    const float* z    = (const float*)d_in[0];   // (8192, 256) f32
    const float* cent = (const float*)d_in[1];   // (64, 256)   f32
    float* Q = (float*)d_out;
    float* P = Q + (size_t)NR * NC;

    cudaFuncSetAttribute(fused_kernel, cudaFuncAttributeMaxDynamicSharedMemorySize, SMEM_B);
    fused_kernel<<<NBLK, TPB, SMEM_B>>>(z, cent, Q, P);
}

// round 13
// speedup vs baseline: 2.1463x; 1.1940x over previous
#include <cuda_runtime.h>
#include <cuda_bf16.h>
#include <math.h>

#define NR   8192     // rows of z
#define HD   256      // feature dim
#define NC   64       // clusters
#define RPB  64       // rows per block
#define TPB  512      // 16 warps: 4 warp_m x 4 warp_n, warp tile m16n16
#define NBLK (NR / RPB)   // 128 blocks, one wave, 1 block/SM

// bf16 tiles [64][256], row stride 512B, XOR-swizzled; 32KB each
#define OFF_Z  0
#define OFF_C  32768
#define SMEM_B 65536

#define FXSCALE 4294967296.0f          // 2^32
#define FXINV   (1.0f / 4294967296.0f)

__device__ unsigned long long g_colfx[2][NC]; // fixed-point colsums, epoch-parity buffered
__device__ unsigned int g_start;      // start ticket counter (epoch source)
__device__ unsigned int g_arrive;     // arrival ticket counter (grid sync)

#define LDSM4(r, addr) \
    asm volatile("ldmatrix.sync.aligned.m8n8.x4.shared.b16 {%0,%1,%2,%3}, [%4];" \
        : "=r"((r)[0]), "=r"((r)[1]), "=r"((r)[2]), "=r"((r)[3]) : "r"(addr))

#define MMA16816(d, a, b0, b1) \
    asm volatile("mma.sync.aligned.m16n8k16.row.col.f32.bf16.bf16.f32 " \
        "{%0,%1,%2,%3},{%4,%5,%6,%7},{%8,%9},{%0,%1,%2,%3};" \
        : "+f"((d)[0]), "+f"((d)[1]), "+f"((d)[2]), "+f"((d)[3]) \
        : "r"((a)[0]), "r"((a)[1]), "r"((a)[2]), "r"((a)[3]), "r"(b0), "r"(b1))

__device__ __forceinline__ unsigned bf2_bits(__nv_bfloat162 h) {
    return *reinterpret_cast<unsigned*>(&h);
}
__device__ __forceinline__ float fsqrt_ap(float x) {
    float r; asm("sqrt.approx.ftz.f32 %0, %1;" : "=f"(r) : "f"(x)); return r;
}
__device__ __forceinline__ float frcp_ap(float x) {
    float r; asm("rcp.approx.ftz.f32 %0, %1;" : "=f"(r) : "f"(x)); return r;
}

__global__ void __launch_bounds__(TPB, 1)
fused_kernel(const float* __restrict__ z, const float* __restrict__ cent,
             float* __restrict__ Q, float* __restrict__ P) {
    extern __shared__ char smem[];
    char* zt = smem + OFF_Z;
    char* ct = smem + OFF_C;
    __shared__ float s_zn[RPB], s_cn[NC];
    __shared__ float s_rsp[4][RPB];    // staged row-sum partials (per wn warp-col)
    __shared__ float s_csp[4][NC];     // staged col-sum partials (per wm warp-row)
    __shared__ float s_ct[NC];         // colsum reciprocals
    __shared__ unsigned s_epoch;

    const int t = threadIdx.x;
    const unsigned sb = (unsigned)__cvta_generic_to_shared(smem);

    // epoch from monotonic start ticket (same value across all blocks of a launch)
    if (t == 0) {
        unsigned st = atomicAdd(&g_start, 1u);
        s_epoch = st / NBLK;
    }

    // ---- Phase 1: issue ALL 16 LDG.128 up front (z + centroids), then convert ----
    {
        const int row = t >> 3;
        const int l8 = t & 7;
        const float4* zg = (const float4*)(z + (size_t)blockIdx.x * RPB * HD);
        const float4* cg = (const float4*)cent;

        float4 vz[8], vc[8];
        #pragma unroll
        for (int j = 0; j < 8; j++) vz[j] = zg[row * (HD / 4) + (l8 + 8 * j)];
        #pragma unroll
        for (int j = 0; j < 8; j++) vc[j] = cg[row * (HD / 4) + (l8 + 8 * j)];

        float az = 0.f, ac = 0.f;
        #pragma unroll
        for (int j = 0; j < 8; j++) {
            const int c4 = l8 + 8 * j;
            const int byteoff = 8 * c4;
            const unsigned off = row * 512 +
                ((((byteoff >> 4) ^ (row & 7)) << 4) | (byteoff & 15));

            az = fmaf(vz[j].x, vz[j].x, az);
            az = fmaf(vz[j].y, vz[j].y, az);
            az = fmaf(vz[j].z, vz[j].z, az);
            az = fmaf(vz[j].w, vz[j].w, az);
            __nv_bfloat162 zh01 = __floats2bfloat162_rn(vz[j].x, vz[j].y);
            __nv_bfloat162 zh23 = __floats2bfloat162_rn(vz[j].z, vz[j].w);
            *(uint2*)(zt + off) = make_uint2(bf2_bits(zh01), bf2_bits(zh23));

            ac = fmaf(vc[j].x, vc[j].x, ac);
            ac = fmaf(vc[j].y, vc[j].y, ac);
            ac = fmaf(vc[j].z, vc[j].z, ac);
            ac = fmaf(vc[j].w, vc[j].w, ac);
            __nv_bfloat162 ch01 = __floats2bfloat162_rn(vc[j].x, vc[j].y);
            __nv_bfloat162 ch23 = __floats2bfloat162_rn(vc[j].z, vc[j].w);
            *(uint2*)(ct + off) = make_uint2(bf2_bits(ch01), bf2_bits(ch23));
        }
        az += __shfl_xor_sync(0xffffffffu, az, 1);
        az += __shfl_xor_sync(0xffffffffu, az, 2);
        az += __shfl_xor_sync(0xffffffffu, az, 4);
        ac += __shfl_xor_sync(0xffffffffu, ac, 1);
        ac += __shfl_xor_sync(0xffffffffu, ac, 2);
        ac += __shfl_xor_sync(0xffffffffu, ac, 4);
        if (l8 == 0) { s_zn[row] = az; s_cn[row] = ac; }
    }
    __syncthreads();   // BAR A

    // ---- Phase 2: bf16 GEMM mainloop (single-term), warp m16n16, k16/step ----
    const int lane = t & 31, wid = t >> 5;
    const int wm = wid >> 2, wn = wid & 3;
    const int tile = lane >> 3, rit = lane & 7;

    const int arow = wm * 16 + rit + 8 * (tile & 1);
    const int acb = tile >> 1;
    const unsigned abase = sb + OFF_Z + arow * 512;
    const int axor = arow & 7;

    const int brow = wn * 16 + rit + 8 * (tile >> 1);
    const int bcb = tile & 1;
    const unsigned bbase = sb + OFF_C + brow * 512;
    const int bxor = brow & 7;

    float d0[4] = {0.f, 0.f, 0.f, 0.f};   // n-half 0
    float d1[4] = {0.f, 0.f, 0.f, 0.f};   // n-half 1

    #pragma unroll
    for (int ks = 0; ks < 16; ks++) {
        const unsigned aoff = (unsigned)(((2 * ks + acb) ^ axor) << 4);
        const unsigned boff = (unsigned)(((2 * ks + bcb) ^ bxor) << 4);
        unsigned a[4], b[4];
        LDSM4(a, abase + aoff);
        LDSM4(b, bbase + boff);
        MMA16816(d0, a, b[0], b[1]);
        MMA16816(d1, a, b[2], b[3]);
    }

    // ---- Phase 3: epilogue -> Q ----
    const int gid = lane >> 2, tig = lane & 3;
    const int R0 = wm * 16 + gid, R1 = R0 + 8;
    const float znA = s_zn[R0], znB = s_zn[R1];
    const int c00 = wn * 16 + 2 * tig;
    const int c10 = c00 + 8;
    const float cnA0 = s_cn[c00], cnA1 = s_cn[c00 + 1];
    const float cnB0 = s_cn[c10], cnB1 = s_cn[c10 + 1];

    float q00 = frcp_ap(1.f + fsqrt_ap(fmaxf(fmaf(-2.f, d0[0], znA + cnA0), 0.f)));
    float q01 = frcp_ap(1.f + fsqrt_ap(fmaxf(fmaf(-2.f, d0[1], znA + cnA1), 0.f)));
    float q02 = frcp_ap(1.f + fsqrt_ap(fmaxf(fmaf(-2.f, d0[2], znB + cnA0), 0.f)));
    float q03 = frcp_ap(1.f + fsqrt_ap(fmaxf(fmaf(-2.f, d0[3], znB + cnA1), 0.f)));
    float q10 = frcp_ap(1.f + fsqrt_ap(fmaxf(fmaf(-2.f, d1[0], znA + cnB0), 0.f)));
    float q11 = frcp_ap(1.f + fsqrt_ap(fmaxf(fmaf(-2.f, d1[1], znA + cnB1), 0.f)));
    float q12 = frcp_ap(1.f + fsqrt_ap(fmaxf(fmaf(-2.f, d1[2], znB + cnB0), 0.f)));
    float q13 = frcp_ap(1.f + fsqrt_ap(fmaxf(fmaf(-2.f, d1[3], znB + cnB1), 0.f)));

    // row sums: shfl over tig lanes, then staged STS (no atomics)
    float rs0 = (q00 + q01) + (q10 + q11);
    float rs1 = (q02 + q03) + (q12 + q13);
    rs0 += __shfl_xor_sync(0xffffffffu, rs0, 1);
    rs0 += __shfl_xor_sync(0xffffffffu, rs0, 2);
    rs1 += __shfl_xor_sync(0xffffffffu, rs1, 1);
    rs1 += __shfl_xor_sync(0xffffffffu, rs1, 2);
    if (tig == 0) { s_rsp[wn][R0] = rs0; s_rsp[wn][R1] = rs1; }
    __syncthreads();   // BAR B

    const float ir0 = frcp_ap(((s_rsp[0][R0] + s_rsp[1][R0]) +
                               (s_rsp[2][R0] + s_rsp[3][R0])));
    const float ir1 = frcp_ap(((s_rsp[0][R1] + s_rsp[1][R1]) +
                               (s_rsp[2][R1] + s_rsp[3][R1])));
    q00 *= ir0; q01 *= ir0; q10 *= ir0; q11 *= ir0;
    q02 *= ir1; q03 *= ir1; q12 *= ir1; q13 *= ir1;

    const int gA = blockIdx.x * RPB + R0;
    const int gB = blockIdx.x * RPB + R1;
    *(float2*)(Q + (size_t)gA * NC + c00) = make_float2(q00, q01);
    *(float2*)(Q + (size_t)gB * NC + c00) = make_float2(q02, q03);
    *(float2*)(Q + (size_t)gA * NC + c10) = make_float2(q10, q11);
    *(float2*)(Q + (size_t)gB * NC + c10) = make_float2(q12, q13);

    // column sums: shfl over gid lanes, staged STS per wm (no atomics)
    float cA0 = q00 + q02, cA1 = q01 + q03;
    float cB0 = q10 + q12, cB1 = q11 + q13;
    #pragma unroll
    for (int m = 4; m <= 16; m <<= 1) {
        cA0 += __shfl_xor_sync(0xffffffffu, cA0, m);
        cA1 += __shfl_xor_sync(0xffffffffu, cA1, m);
        cB0 += __shfl_xor_sync(0xffffffffu, cB0, m);
        cB1 += __shfl_xor_sync(0xffffffffu, cB1, m);
    }
    if (lane < 4) {
        s_csp[wm][c00]     = cA0;
        s_csp[wm][c00 + 1] = cA1;
        s_csp[wm][c10]     = cB0;
        s_csp[wm][c10 + 1] = cB1;
    }
    __syncthreads();   // BAR C

    // deterministic fixed-point global colsum reduction + zero the other buffer
    const unsigned buf = s_epoch & 1u;
    if (t < NC) {
        float s = (s_csp[0][t] + s_csp[1][t]) + (s_csp[2][t] + s_csp[3][t]);
        long long fx = llrintf(s * FXSCALE);
        atomicAdd(&g_colfx[buf][t], (unsigned long long)fx);
        g_colfx[buf ^ 1u][t] = 0ull;   // prepare next launch's buffer (idempotent)
    }
    __syncthreads();   // BAR D

    // ---- single-wave grid sync (epoch ticket; release/acquire ordering) ----
    if (t == 0) {
        unsigned ticket;
        asm volatile("atom.global.add.release.gpu.u32 %0, [%1], 1;"
                     : "=r"(ticket) : "l"(&g_arrive) : "memory");
        const unsigned target = (ticket / NBLK + 1u) * NBLK;
        unsigned v;
        while (true) {
            asm volatile("ld.global.acquire.gpu.u32 %0, [%1];"
                         : "=r"(v) : "l"(&g_arrive) : "memory");
            if (v >= target) break;
            __nanosleep(32);
        }
    }
    __syncthreads();   // BAR E

    // read final colsums (256B total) -> reciprocals
    if (t < NC) {
        unsigned long long v = __ldcg(&g_colfx[buf][t]);
        s_ct[t] = frcp_ap((float)v * FXINV);
    }
    __syncthreads();   // BAR F

    // ---- Phase 4: P from in-register Q ----
    const float icA0 = s_ct[c00], icA1 = s_ct[c00 + 1];
    const float icB0 = s_ct[c10], icB1 = s_ct[c10 + 1];

    float p00 = q00 * q00 * icA0, p01 = q01 * q01 * icA1;
    float p02 = q02 * q02 * icA0, p03 = q03 * q03 * icA1;
    float p10 = q10 * q10 * icB0, p11 = q11 * q11 * icB1;
    float p12 = q12 * q12 * icB0, p13 = q13 * q13 * icB1;

    float ps0 = (p00 + p01) + (p10 + p11);
    float ps1 = (p02 + p03) + (p12 + p13);
    ps0 += __shfl_xor_sync(0xffffffffu, ps0, 1);
    ps0 += __shfl_xor_sync(0xffffffffu, ps0, 2);
    ps1 += __shfl_xor_sync(0xffffffffu, ps1, 1);
    ps1 += __shfl_xor_sync(0xffffffffu, ps1, 2);
    if (tig == 0) { s_rsp[wn][R0] = ps0; s_rsp[wn][R1] = ps1; }
    __syncthreads();   // BAR G

    const float ip0 = frcp_ap(((s_rsp[0][R0] + s_rsp[1][R0]) +
                               (s_rsp[2][R0] + s_rsp[3][R0])));
    const float ip1 = frcp_ap(((s_rsp[0][R1] + s_rsp[1][R1]) +
                               (s_rsp[2][R1] + s_rsp[3][R1])));
    *(float2*)(P + (size_t)gA * NC + c00) = make_float2(p00 * ip0, p01 * ip0);
    *(float2*)(P + (size_t)gB * NC + c00) = make_float2(p02 * ip1, p03 * ip1);
    *(float2*)(P + (size_t)gA * NC + c10) = make_float2(p10 * ip0, p11 * ip0);
    *(float2*)(P + (size_t)gB * NC + c10) = make_float2(p12 * ip1, p13 * ip1);
}

extern "C" void kernel_launch(void* const* d_in, const int* in_sizes, int n_in,
                              void* d_out, int out_size) {
    const float* z    = (const float*)d_in[0];   // (8192, 256) f32
    const float* cent = (const float*)d_in[1];   // (64, 256)   f32
    float* Q = (float*)d_out;
    float* P = Q + (size_t)NR * NC;

    cudaFuncSetAttribute(fused_kernel, cudaFuncAttributeMaxDynamicSharedMemorySize, SMEM_B);
    fused_kernel<<<NBLK, TPB, SMEM_B>>>(z, cent, Q, P);
}